// round 11
// baseline (speedup 1.0000x reference)
#include <cuda_runtime.h>

// StyleGAN 3D x2 upsample, separable [1,4,6,4,1]/16 * 2 per axis.
// Per axis: out[2m]   = 0.5*(x[m-1] + x[m])
//           out[2m+1] = 0.125*x[m-1] + 0.75*x[m] + 0.125*x[m+1]
//
// PERSISTENT grid-stride version: 592 blocks (=148 SMs x 4) each process
// 7-8 tiles. No wave transitions; previous tile's TMA bulk stores drain
// during the next tile's cp.async fill, so the DRAM write stream stays hot.
// Tile body identical to the best-known pipeline (R10).

#define DIN   48
#define DOUT  96
#define TD    8            // input-d per tile
#define TH    8            // input-h per tile
#define SD    10           // TD + 2 halo
#define SHH   10           // TH + 2 halo
#define SWR   56           // zeros[0..3], x[4..51], zeros[52..55]

#define NTILE_D   (DIN / TD)             // 6
#define NTILE_H   (DIN / TH)             // 6
#define NTILE_NC  128
#define NTILES    (NTILE_D * NTILE_H * NTILE_NC)   // 4608
#define NBLOCKS   592                    // 148 SMs x 4 resident blocks

__device__ __forceinline__ unsigned sm32(const void* p) {
    return (unsigned)__cvta_generic_to_shared(p);
}

__global__ __launch_bounds__(192, 4)
void upsample3d_kernel(const float* __restrict__ in, float* __restrict__ out)
{
    __shared__ float s2[SD][SHH][SWR];            // raw input tile (21.9 KB)
    __shared__ float stg[2][2][2 * TH][DOUT];     // staging: 2 bufs x 2 planes (24 KB)

    const int tx = threadIdx.x;            // 0..23  (output w quad = 4tx)
    const int ty = threadIdx.y;            // 0..7   (input h in tile)
    const int tid = ty * 24 + tx;          // 0..191

    int q = 0;                             // global output-pair counter (buf parity)

    for (int t = blockIdx.x; t < NTILES; t += NBLOCKS) {
        const int nc  = t / (NTILE_D * NTILE_H);
        const int rem = t % (NTILE_D * NTILE_H);
        const int d0  = (rem / NTILE_H) * TD;
        const int h0  = (rem % NTILE_H) * TH;

        const float* __restrict__ src = in  + (size_t)nc * (DIN * DIN * DIN);
        float*       __restrict__ dst = out + (size_t)nc * ((size_t)DOUT * DOUT * DOUT);

        // ================= Stage A: async fill (1200 float4 tasks) ==========
        for (int i = tid; i < SD * SHH * 12; i += 192) {
            const int c  = i % 12;
            const int r  = i / 12;
            const int rh = r % SHH;
            const int rd = r / SHH;
            const int h  = rh - 1 + h0;
            const int d  = rd - 1 + d0;
            const bool ok = ((unsigned)h < DIN) && ((unsigned)d < DIN);
            const float* gp = src + ((size_t)d * DIN + h) * DIN + 4 * c;
            const unsigned sp = sm32(&s2[rd][rh][4 + 4 * c]);
            const int nbytes = ok ? 16 : 0;    // zfill when OOB
            asm volatile("cp.async.ca.shared.global [%0], [%1], 16, %2;"
                         :: "r"(sp), "l"(gp), "r"(nbytes) : "memory");
        }
        for (int i = tid; i < SD * SHH * 2; i += 192) {   // w-halo pads
            const int r = i >> 1;
            *(float4*)&s2[r / SHH][r % SHH][(i & 1) ? 52 : 0] =
                make_float4(0.f, 0.f, 0.f, 0.f);
        }
        asm volatile("cp.async.commit_group;" ::: "memory");
        asm volatile("cp.async.wait_group 0;" ::: "memory");
        __syncthreads();

        // ================= Stage B: W+H+D rolling ring, bulk-copied out =====
        const int wb = 2 * tx + 3;             // s2 index of x[2tx-1]
        float4 hv[3][2];                       // ring of H results (even-h, odd-h)

        #pragma unroll
        for (int i = 0; i < SD; i++) {
            // ---- W then H for d-window row i (once per row) ----
            float4 w[3];
            #pragma unroll
            for (int j = 0; j < 3; j++) {
                const float* row = s2[i][ty + j];
                float  a  = row[wb];                          // x[2tx-1]
                float2 bc = *(const float2*)&row[wb + 1];     // x[2tx], x[2tx+1]
                float  dd = row[wb + 3];                      // x[2tx+2]
                w[j].x = 0.5f  * (a + bc.x);
                w[j].y = 0.75f * bc.x + 0.125f * (a + bc.y);
                w[j].z = 0.5f  * (bc.x + bc.y);
                w[j].w = 0.75f * bc.y + 0.125f * (bc.x + dd);
            }
            {
                float4 e, o;
                e.x = 0.5f * (w[0].x + w[1].x);  o.x = 0.75f * w[1].x + 0.125f * (w[0].x + w[2].x);
                e.y = 0.5f * (w[0].y + w[1].y);  o.y = 0.75f * w[1].y + 0.125f * (w[0].y + w[2].y);
                e.z = 0.5f * (w[0].z + w[1].z);  o.z = 0.75f * w[1].z + 0.125f * (w[0].z + w[2].z);
                e.w = 0.5f * (w[0].w + w[1].w);  o.w = 0.75f * w[1].w + 0.125f * (w[0].w + w[2].w);
                hv[i % 3][0] = e;
                hv[i % 3][1] = o;
            }

            // ---- D-pass for output pair p = i-2 ----
            if (i >= 2) {
                const int p   = i - 2;         // 0..TD-1
                const int buf = q & 1;         // parity continuous across tiles

                float4 vE[2], vO[2];
                #pragma unroll
                for (int hs = 0; hs < 2; hs++) {
                    float4 A = hv[(i - 2) % 3][hs];
                    float4 B = hv[(i - 1) % 3][hs];
                    float4 C = hv[i % 3][hs];
                    vE[hs].x = 0.5f * (A.x + B.x);  vO[hs].x = 0.75f * B.x + 0.125f * (A.x + C.x);
                    vE[hs].y = 0.5f * (A.y + B.y);  vO[hs].y = 0.75f * B.y + 0.125f * (A.y + C.y);
                    vE[hs].z = 0.5f * (A.z + B.z);  vO[hs].z = 0.75f * B.z + 0.125f * (A.z + C.z);
                    vE[hs].w = 0.5f * (A.w + B.w);  vO[hs].w = 0.75f * B.w + 0.125f * (A.w + C.w);
                }

                // buffer (q&1) was consumed by bulk group q-2; wait for its reads
                if (q >= 2 && tid == 0)
                    asm volatile("cp.async.bulk.wait_group.read 1;" ::: "memory");
                __syncthreads();

                #pragma unroll
                for (int hs = 0; hs < 2; hs++) {
                    *(float4*)&stg[buf][0][2 * ty + hs][4 * tx] = vE[hs];
                    *(float4*)&stg[buf][1][2 * ty + hs][4 * tx] = vO[hs];
                }
                __syncthreads();

                if (tid == 0) {
                    asm volatile("fence.proxy.async.shared::cta;" ::: "memory");
                    const int od = 2 * (d0 + p);
                    float* g0 = dst + ((size_t)od * DOUT + 2 * h0) * DOUT;
                    float* g1 = g0 + (size_t)DOUT * DOUT;
                    asm volatile(
                        "cp.async.bulk.global.shared::cta.bulk_group [%0], [%1], %2;"
                        :: "l"(g0), "r"(sm32(&stg[buf][0][0][0])),
                           "r"(2 * TH * DOUT * 4) : "memory");
                    asm volatile(
                        "cp.async.bulk.global.shared::cta.bulk_group [%0], [%1], %2;"
                        :: "l"(g1), "r"(sm32(&stg[buf][1][0][0])),
                           "r"(2 * TH * DOUT * 4) : "memory");
                    asm volatile("cp.async.bulk.commit_group;" ::: "memory");
                }
                q++;
            }
        }
        // NOTE: no full drain here — prev tile's stores overlap next tile's fill.
        // s2 reuse is safe: every thread passed the staging barriers after its
        // last s2 read of this tile.
    }

    // drain all outstanding bulk stores before exit
    if (tid == 0)
        asm volatile("cp.async.bulk.wait_group 0;" ::: "memory");
}

extern "C" void kernel_launch(void* const* d_in, const int* in_sizes, int n_in,
                              void* d_out, int out_size)
{
    const float* x = (const float*)d_in[0];
    float* y = (float*)d_out;
    dim3 block(24, 8, 1);                        // 192 threads
    upsample3d_kernel<<<NBLOCKS, block>>>(x, y); // persistent: 592 blocks
}

// round 12
// speedup vs baseline: 1.1777x; 1.1777x over previous
#include <cuda_runtime.h>

// StyleGAN 3D x2 upsample, separable [1,4,6,4,1]/16 * 2 per axis.
// Per axis: out[2m]   = 0.5*(x[m-1] + x[m])
//           out[2m+1] = 0.125*x[m-1] + 0.75*x[m] + 0.125*x[m+1]
//
// Stage A: raw tile -> smem via cp.async (LDGSTS, zfill OOB), split into
// TWO commit groups (d-rows 0..5 / 6..9) so Stage B (and its TMA stores)
// starts while the second half of the fill is still in flight.
// Stage B: rolling 3-row ring, W+H fused; D-pass staged in double-buffered
// smem, drained via cp.async.bulk S->G with L2::evict_first (protects the
// L2-resident input from streaming-output eviction).

#define DIN   48
#define DOUT  96
#define TD    8            // input-d per tile
#define TH    8            // input-h per tile
#define SD    10           // TD + 2 halo
#define SHH   10           // TH + 2 halo
#define SWR   56           // zeros[0..3], x[4..51], zeros[52..55]

#define FILL_SPLIT_ROW 6                       // group A covers d-rows 0..5
#define FILL_SPLIT    (FILL_SPLIT_ROW * SHH * 12)
#define FILL_TOTAL    (SD * SHH * 12)

__device__ __forceinline__ unsigned sm32(const void* p) {
    return (unsigned)__cvta_generic_to_shared(p);
}

__global__ __launch_bounds__(192, 4)
void upsample3d_kernel(const float* __restrict__ in, float* __restrict__ out)
{
    __shared__ float s2[SD][SHH][SWR];            // raw input tile (21.9 KB)
    __shared__ float stg[2][2][2 * TH][DOUT];     // staging: 2 bufs x 2 planes (24 KB)

    const int tx = threadIdx.x;            // 0..23  (output w quad = 4tx)
    const int ty = threadIdx.y;            // 0..7   (input h in tile)
    const int h0 = blockIdx.x * TH;
    const int d0 = blockIdx.y * TD;
    const int nc = blockIdx.z;             // fused N*C = 128

    const float* __restrict__ src = in  + (size_t)nc * (DIN * DIN * DIN);
    float*       __restrict__ dst = out + (size_t)nc * ((size_t)DOUT * DOUT * DOUT);

    const int tid = ty * 24 + tx;          // 0..191

    unsigned long long pol;                // L2 evict-first policy for stores
    asm volatile("createpolicy.fractional.L2::evict_first.b64 %0, 1.0;" : "=l"(pol));

    // ================= Stage A: async fill, two commit groups ===============
    // Group A: d-rows 0..FILL_SPLIT_ROW-1
    for (int i = tid; i < FILL_SPLIT; i += 192) {
        const int c  = i % 12;
        const int r  = i / 12;
        const int rh = r % SHH;
        const int rd = r / SHH;
        const int h  = rh - 1 + h0;
        const int d  = rd - 1 + d0;
        const bool ok = ((unsigned)h < DIN) && ((unsigned)d < DIN);
        const float* gp = src + ((size_t)d * DIN + h) * DIN + 4 * c;
        const unsigned sp = sm32(&s2[rd][rh][4 + 4 * c]);
        const int nbytes = ok ? 16 : 0;    // zfill when OOB
        asm volatile("cp.async.ca.shared.global [%0], [%1], 16, %2;"
                     :: "r"(sp), "l"(gp), "r"(nbytes) : "memory");
    }
    asm volatile("cp.async.commit_group;" ::: "memory");
    // Group B: d-rows FILL_SPLIT_ROW..SD-1
    for (int i = FILL_SPLIT + tid; i < FILL_TOTAL; i += 192) {
        const int c  = i % 12;
        const int r  = i / 12;
        const int rh = r % SHH;
        const int rd = r / SHH;
        const int h  = rh - 1 + h0;
        const int d  = rd - 1 + d0;
        const bool ok = ((unsigned)h < DIN) && ((unsigned)d < DIN);
        const float* gp = src + ((size_t)d * DIN + h) * DIN + 4 * c;
        const unsigned sp = sm32(&s2[rd][rh][4 + 4 * c]);
        const int nbytes = ok ? 16 : 0;
        asm volatile("cp.async.ca.shared.global [%0], [%1], 16, %2;"
                     :: "r"(sp), "l"(gp), "r"(nbytes) : "memory");
    }
    asm volatile("cp.async.commit_group;" ::: "memory");

    // w-halo pads (disjoint bytes from the async fills)
    for (int i = tid; i < SD * SHH * 2; i += 192) {
        const int r = i >> 1;
        *(float4*)&s2[r / SHH][r % SHH][(i & 1) ? 52 : 0] =
            make_float4(0.f, 0.f, 0.f, 0.f);
    }

    // wait for group A only (group B still in flight)
    asm volatile("cp.async.wait_group 1;" ::: "memory");
    __syncthreads();

    // ================= Stage B: W+H+D rolling ring, bulk-copied out =========
    const int wb = 2 * tx + 3;             // s2 index of x[2tx-1]
    float4 hv[3][2];                       // ring of H results (even-h, odd-h)

    #pragma unroll
    for (int i = 0; i < SD; i++) {
        // second fill group must have landed before reading d-row >= split
        if (i == FILL_SPLIT_ROW) {
            asm volatile("cp.async.wait_group 0;" ::: "memory");
            __syncthreads();
        }

        // ---- W then H for d-window row i (once per row) ----
        float4 w[3];
        #pragma unroll
        for (int j = 0; j < 3; j++) {
            const float* row = s2[i][ty + j];
            float  a  = row[wb];                          // x[2tx-1]
            float2 bc = *(const float2*)&row[wb + 1];     // x[2tx], x[2tx+1]
            float  dd = row[wb + 3];                      // x[2tx+2]
            w[j].x = 0.5f  * (a + bc.x);
            w[j].y = 0.75f * bc.x + 0.125f * (a + bc.y);
            w[j].z = 0.5f  * (bc.x + bc.y);
            w[j].w = 0.75f * bc.y + 0.125f * (bc.x + dd);
        }
        {
            float4 e, o;
            e.x = 0.5f * (w[0].x + w[1].x);  o.x = 0.75f * w[1].x + 0.125f * (w[0].x + w[2].x);
            e.y = 0.5f * (w[0].y + w[1].y);  o.y = 0.75f * w[1].y + 0.125f * (w[0].y + w[2].y);
            e.z = 0.5f * (w[0].z + w[1].z);  o.z = 0.75f * w[1].z + 0.125f * (w[0].z + w[2].z);
            e.w = 0.5f * (w[0].w + w[1].w);  o.w = 0.75f * w[1].w + 0.125f * (w[0].w + w[2].w);
            hv[i % 3][0] = e;
            hv[i % 3][1] = o;
        }

        // ---- D-pass for output pair p = i-2 ----
        if (i >= 2) {
            const int p   = i - 2;         // 0..TD-1 (compile-time after unroll)
            const int buf = p & 1;

            float4 vE[2], vO[2];
            #pragma unroll
            for (int hs = 0; hs < 2; hs++) {
                float4 A = hv[(i - 2) % 3][hs];
                float4 B = hv[(i - 1) % 3][hs];
                float4 C = hv[i % 3][hs];
                vE[hs].x = 0.5f * (A.x + B.x);  vO[hs].x = 0.75f * B.x + 0.125f * (A.x + C.x);
                vE[hs].y = 0.5f * (A.y + B.y);  vO[hs].y = 0.75f * B.y + 0.125f * (A.y + C.y);
                vE[hs].z = 0.5f * (A.z + B.z);  vO[hs].z = 0.75f * B.z + 0.125f * (A.z + C.z);
                vE[hs].w = 0.5f * (A.w + B.w);  vO[hs].w = 0.75f * B.w + 0.125f * (A.w + C.w);
            }

            // buffer (p&1) was consumed by bulk group p-2; wait for its reads
            if (p >= 2 && tid == 0)
                asm volatile("cp.async.bulk.wait_group.read 1;" ::: "memory");
            __syncthreads();

            #pragma unroll
            for (int hs = 0; hs < 2; hs++) {
                *(float4*)&stg[buf][0][2 * ty + hs][4 * tx] = vE[hs];
                *(float4*)&stg[buf][1][2 * ty + hs][4 * tx] = vO[hs];
            }
            __syncthreads();

            if (tid == 0) {
                asm volatile("fence.proxy.async.shared::cta;" ::: "memory");
                const int od = 2 * (d0 + p);
                float* g0 = dst + ((size_t)od * DOUT + 2 * h0) * DOUT;
                float* g1 = g0 + (size_t)DOUT * DOUT;
                asm volatile(
                    "cp.async.bulk.global.shared::cta.bulk_group.L2::cache_hint "
                    "[%0], [%1], %2, %3;"
                    :: "l"(g0), "r"(sm32(&stg[buf][0][0][0])),
                       "r"(2 * TH * DOUT * 4), "l"(pol) : "memory");
                asm volatile(
                    "cp.async.bulk.global.shared::cta.bulk_group.L2::cache_hint "
                    "[%0], [%1], %2, %3;"
                    :: "l"(g1), "r"(sm32(&stg[buf][1][0][0])),
                       "r"(2 * TH * DOUT * 4), "l"(pol) : "memory");
                asm volatile("cp.async.bulk.commit_group;" ::: "memory");
            }
        }
    }

    // drain all outstanding bulk stores before exit
    if (tid == 0)
        asm volatile("cp.async.bulk.wait_group 0;" ::: "memory");
}

extern "C" void kernel_launch(void* const* d_in, const int* in_sizes, int n_in,
                              void* d_out, int out_size)
{
    const float* x = (const float*)d_in[0];
    float* y = (float*)d_out;
    dim3 block(24, 8, 1);                        // 192 threads
    dim3 grid(DIN / TH, DIN / TD, 128);          // 6 x 6 x (N*C) = 4608 blocks
    upsample3d_kernel<<<grid, block>>>(x, y);
}